// round 8
// baseline (speedup 1.0000x reference)
#include <cuda_runtime.h>

#define VOCAB 32000
#define BATCH 4
#define SEQ   2048
#define NVEC  (VOCAB / 4)        // 8000 float4 per row
#define N4    ((BATCH * VOCAB) / 4)

// Scratch histogram. Zero-initialized at module load; finalize_kernel resets
// it to zero after consuming it, so it is zero at every argmax entry
// (correctness run and every graph replay).
__device__ int g_hist[BATCH * VOCAB];

// Warp-per-row argmax: 2048 CTAs x 4 warps; warp w handles row
// blockIdx.x*4 + w, scanning the FULL row (NVEC float4, 250 per lane).
// No shared memory, no __syncthreads — warp-local reduction only, so the
// scheduler always has eligible warps during any warp's epilogue.
__global__ __launch_bounds__(128)
void argmax_hist_kernel(const float* __restrict__ logits) {
    const int wid = threadIdx.x >> 5;
    const int lid = threadIdx.x & 31;
    const int row = (blockIdx.x << 2) + wid;          // 0 .. B*S-1
    const float4* __restrict__ p =
        reinterpret_cast<const float4*>(logits + (size_t)row * VOCAB);

    float best = -3.402823466e+38f;
    int   bidx = 0;

    // Lane-strided float4 scan over the full row (NVEC = 8000 float4,
    // 250 per lane), streaming loads, unroll 8 for deep MLP. Strict '>'
    // keeps the first (lowest-index) max within a lane; combined with the
    // smaller-index tie-break in the reduction this matches jnp.argmax.
    #pragma unroll 8
    for (int i = lid; i < NVEC; i += 32) {
        float4 v = __ldcs(p + i);
        int base = i << 2;
        if (v.x > best) { best = v.x; bidx = base;     }
        if (v.y > best) { best = v.y; bidx = base + 1; }
        if (v.z > best) { best = v.z; bidx = base + 2; }
        if (v.w > best) { best = v.w; bidx = base + 3; }
    }

    // Warp reduction (tie -> smaller index)
    #pragma unroll
    for (int off = 16; off > 0; off >>= 1) {
        float ov = __shfl_down_sync(0xFFFFFFFFu, best, off);
        int   oi = __shfl_down_sync(0xFFFFFFFFu, bidx, off);
        if (ov > best || (ov == best && oi < bidx)) { best = ov; bidx = oi; }
    }

    if (lid == 0) {
        const int b = row >> 11;                      // row / SEQ
        atomicAdd(&g_hist[b * VOCAB + bidx], 1);
    }
}

// out[b, v] = (v is special) ? 0 : min(hist, 4) / 4 ; also resets g_hist to 0
// so the next kernel_launch (graph replay) sees a clean histogram.
__global__ void finalize_kernel(float* __restrict__ out) {
    const int i = blockIdx.x * blockDim.x + threadIdx.x;   // int4 index
    if (i < N4) {
        int4* hp = reinterpret_cast<int4*>(g_hist) + i;
        int4 h = *hp;
        *hp = make_int4(0, 0, 0, 0);

        const int e0 = i << 2;
        const int v0 = e0 % VOCAB;   // VOCAB % 4 == 0 -> whole int4 in one row

        float4 o;
        o.x = (v0     <= 2) ? 0.0f : fminf((float)h.x, 4.0f) * 0.25f;
        o.y = (v0 + 1 <= 2) ? 0.0f : fminf((float)h.y, 4.0f) * 0.25f;
        o.z = (v0 + 2 <= 2) ? 0.0f : fminf((float)h.z, 4.0f) * 0.25f;
        o.w = (v0 + 3 <= 2) ? 0.0f : fminf((float)h.w, 4.0f) * 0.25f;
        reinterpret_cast<float4*>(out)[i] = o;
    }
}

extern "C" void kernel_launch(void* const* d_in, const int* in_sizes, int n_in,
                              void* d_out, int out_size) {
    const float* logits = (const float*)d_in[0];
    float* out = (float*)d_out;

    argmax_hist_kernel<<<(BATCH * SEQ) / 4, 128>>>(logits);
    finalize_kernel<<<(N4 + 255) / 256, 256>>>(out);
}

// round 9
// speedup vs baseline: 1.0269x; 1.0269x over previous
#include <cuda_runtime.h>

#define VOCAB 32000
#define BATCH 4
#define SEQ   2048
#define NVEC  (VOCAB / 4)   // 8000 float4 per row
#define N4    ((BATCH * VOCAB) / 4)

// Scratch histogram. Zero-initialized at module load; finalize_kernel resets
// it to zero after consuming it, so it is zero at every argmax entry
// (correctness run and every graph replay).
__device__ int g_hist[BATCH * VOCAB];

// One CTA per (b, s) row: argmax over VOCAB, then atomicAdd into histogram.
__global__ __launch_bounds__(256, 8)
void argmax_hist_kernel(const float* __restrict__ logits) {
    const int row = blockIdx.x;                       // 0 .. B*S-1
    const float4* __restrict__ p =
        reinterpret_cast<const float4*>(logits + (size_t)row * VOCAB);

    float best = -3.402823466e+38f;
    int   bidx = 0;
    const int tid = threadIdx.x;

    // Strided float4 scan, streaming (evict-first) loads, unroll 8 for a
    // deeper front-batched LDG window (better DRAM latency coverage).
    // Strict '>' keeps the first (lowest-index) max within a thread,
    // matching jnp.argmax first-hit semantics.
    #pragma unroll 8
    for (int i = tid; i < NVEC; i += 256) {
        float4 v = __ldcs(p + i);
        int base = i << 2;
        if (v.x > best) { best = v.x; bidx = base;     }
        if (v.y > best) { best = v.y; bidx = base + 1; }
        if (v.z > best) { best = v.z; bidx = base + 2; }
        if (v.w > best) { best = v.w; bidx = base + 3; }
    }

    // Warp reduction (tie -> smaller index)
    #pragma unroll
    for (int off = 16; off > 0; off >>= 1) {
        float ov = __shfl_down_sync(0xFFFFFFFFu, best, off);
        int   oi = __shfl_down_sync(0xFFFFFFFFu, bidx, off);
        if (ov > best || (ov == best && oi < bidx)) { best = ov; bidx = oi; }
    }

    __shared__ float s_val[8];
    __shared__ int   s_idx[8];
    const int wid = tid >> 5;
    const int lid = tid & 31;
    if (lid == 0) { s_val[wid] = best; s_idx[wid] = bidx; }
    __syncthreads();

    if (wid == 0) {
        best = (lid < 8) ? s_val[lid] : -3.402823466e+38f;
        bidx = (lid < 8) ? s_idx[lid] : 0x7FFFFFFF;
        #pragma unroll
        for (int off = 4; off > 0; off >>= 1) {
            float ov = __shfl_down_sync(0xFFFFFFFFu, best, off);
            int   oi = __shfl_down_sync(0xFFFFFFFFu, bidx, off);
            if (ov > best || (ov == best && oi < bidx)) { best = ov; bidx = oi; }
        }
        if (lid == 0) {
            int b = row / SEQ;
            atomicAdd(&g_hist[b * VOCAB + bidx], 1);
        }
    }
}

// out[b, v] = (v is special) ? 0 : min(hist, 4) / 4 ; also resets g_hist to 0
// so the next kernel_launch (graph replay) sees a clean histogram. The reset
// store is skipped when the entry is already zero (~94% of entries), cutting
// most of the reset write traffic.
__global__ void finalize_kernel(float* __restrict__ out) {
    const int i = blockIdx.x * blockDim.x + threadIdx.x;   // int4 index
    if (i < N4) {
        int4* hp = reinterpret_cast<int4*>(g_hist) + i;
        int4 h = *hp;
        if (h.x | h.y | h.z | h.w)                   // only reset touched lines
            *hp = make_int4(0, 0, 0, 0);

        const int e0 = i << 2;
        const int v0 = e0 % VOCAB;   // VOCAB % 4 == 0 -> whole int4 in one row

        float4 o;
        o.x = (v0     <= 2) ? 0.0f : fminf((float)h.x, 4.0f) * 0.25f;
        o.y = (v0 + 1 <= 2) ? 0.0f : fminf((float)h.y, 4.0f) * 0.25f;
        o.z = (v0 + 2 <= 2) ? 0.0f : fminf((float)h.z, 4.0f) * 0.25f;
        o.w = (v0 + 3 <= 2) ? 0.0f : fminf((float)h.w, 4.0f) * 0.25f;
        reinterpret_cast<float4*>(out)[i] = o;
    }
}

extern "C" void kernel_launch(void* const* d_in, const int* in_sizes, int n_in,
                              void* d_out, int out_size) {
    const float* logits = (const float*)d_in[0];
    float* out = (float*)d_out;

    argmax_hist_kernel<<<BATCH * SEQ, 256>>>(logits);
    finalize_kernel<<<(N4 + 127) / 128, 128>>>(out);
}

// round 12
// speedup vs baseline: 1.0471x; 1.0196x over previous
#include <cuda_runtime.h>

#define VOCAB 32000
#define BATCH 4
#define SEQ   2048
#define NVEC  (VOCAB / 4)   // 8000 float4 per row
#define N4    ((BATCH * VOCAB) / 4)

// Scratch histogram. Zero-initialized at module load; finalize_kernel resets
// it to zero after consuming it, so it is zero at every argmax entry
// (correctness run and every graph replay).
__device__ int g_hist[BATCH * VOCAB];

// One CTA per (b, s) row: argmax over VOCAB, then atomicAdd into histogram.
// (Exactly the R2 configuration: unroll 4 + __ldcs measured at ~141.7us,
// 7.4 TB/s; unroll 8 measured ~7us slower — keep unroll 4.)
__global__ __launch_bounds__(256, 8)
void argmax_hist_kernel(const float* __restrict__ logits) {
    const int row = blockIdx.x;                       // 0 .. B*S-1
    const float4* __restrict__ p =
        reinterpret_cast<const float4*>(logits + (size_t)row * VOCAB);

    float best = -3.402823466e+38f;
    int   bidx = 0;
    const int tid = threadIdx.x;

    // Strided float4 scan, streaming (evict-first) loads. Strict '>' keeps
    // the first (lowest-index) max within a thread, matching jnp.argmax.
    #pragma unroll 4
    for (int i = tid; i < NVEC; i += 256) {
        float4 v = __ldcs(p + i);
        int base = i << 2;
        if (v.x > best) { best = v.x; bidx = base;     }
        if (v.y > best) { best = v.y; bidx = base + 1; }
        if (v.z > best) { best = v.z; bidx = base + 2; }
        if (v.w > best) { best = v.w; bidx = base + 3; }
    }

    // Warp reduction (tie -> smaller index)
    #pragma unroll
    for (int off = 16; off > 0; off >>= 1) {
        float ov = __shfl_down_sync(0xFFFFFFFFu, best, off);
        int   oi = __shfl_down_sync(0xFFFFFFFFu, bidx, off);
        if (ov > best || (ov == best && oi < bidx)) { best = ov; bidx = oi; }
    }

    __shared__ float s_val[8];
    __shared__ int   s_idx[8];
    const int wid = tid >> 5;
    const int lid = tid & 31;
    if (lid == 0) { s_val[wid] = best; s_idx[wid] = bidx; }
    __syncthreads();

    if (wid == 0) {
        best = (lid < 8) ? s_val[lid] : -3.402823466e+38f;
        bidx = (lid < 8) ? s_idx[lid] : 0x7FFFFFFF;
        #pragma unroll
        for (int off = 4; off > 0; off >>= 1) {
            float ov = __shfl_down_sync(0xFFFFFFFFu, best, off);
            int   oi = __shfl_down_sync(0xFFFFFFFFu, bidx, off);
            if (ov > best || (ov == best && oi < bidx)) { best = ov; bidx = oi; }
        }
        if (lid == 0) {
            int b = row / SEQ;
            atomicAdd(&g_hist[b * VOCAB + bidx], 1);
        }
    }
}

// out[b, v] = (v is special) ? 0 : min(hist, 4) / 4 ; also resets g_hist to 0
// so the next kernel_launch (graph replay) sees a clean histogram. The reset
// store is skipped when the entry is already zero (~94% of entries).
// (Exactly the R9 configuration: measured 4.42us.)
__global__ void finalize_kernel(float* __restrict__ out) {
    const int i = blockIdx.x * blockDim.x + threadIdx.x;   // int4 index
    if (i < N4) {
        int4* hp = reinterpret_cast<int4*>(g_hist) + i;
        int4 h = *hp;
        if (h.x | h.y | h.z | h.w)                   // only reset touched lines
            *hp = make_int4(0, 0, 0, 0);

        const int e0 = i << 2;
        const int v0 = e0 % VOCAB;   // VOCAB % 4 == 0 -> whole int4 in one row

        float4 o;
        o.x = (v0     <= 2) ? 0.0f : fminf((float)h.x, 4.0f) * 0.25f;
        o.y = (v0 + 1 <= 2) ? 0.0f : fminf((float)h.y, 4.0f) * 0.25f;
        o.z = (v0 + 2 <= 2) ? 0.0f : fminf((float)h.z, 4.0f) * 0.25f;
        o.w = (v0 + 3 <= 2) ? 0.0f : fminf((float)h.w, 4.0f) * 0.25f;
        reinterpret_cast<float4*>(out)[i] = o;
    }
}

extern "C" void kernel_launch(void* const* d_in, const int* in_sizes, int n_in,
                              void* d_out, int out_size) {
    const float* logits = (const float*)d_in[0];
    float* out = (float*)d_out;

    argmax_hist_kernel<<<BATCH * SEQ, 256>>>(logits);
    finalize_kernel<<<(N4 + 127) / 128, 128>>>(out);
}